// round 1
// baseline (speedup 1.0000x reference)
#include <cuda_runtime.h>

#define S_LEN 2048
#define BATCH 4
#define HEADS 16
#define DH 64
#define DIN 1024
#define M_TOT (BATCH * S_LEN)  // 8192

// ---------------- scratch (allocation-free: __device__ globals) ----------------
__device__ float g_q[BATCH * HEADS * S_LEN * DH];     // [B,H,S,64]
__device__ float g_k[BATCH * HEADS * S_LEN * DH];
__device__ float g_v[BATCH * HEADS * S_LEN * DH];
__device__ float g_attn[M_TOT * HEADS * DH];          // [m][h*64+e]

// ======================= QKV projection GEMM =======================
// grid: (M_TOT/128, HEADS, 3 {q,k,v}); block 256.
// C[128x64] tile: per-head GEMM [8192x1024] x [1024x64] + bias,
// output scattered to [B,H,S,64].
#define BM 128
#define BN 64
#define BK 32

__global__ __launch_bounds__(256) void qkv_gemm(
    const float* __restrict__ x,
    const float* __restrict__ Wq, const float* __restrict__ bq,
    const float* __restrict__ Wk, const float* __restrict__ bk,
    const float* __restrict__ Wv, const float* __restrict__ bv)
{
    const int h = blockIdx.y;
    const int p = blockIdx.z;
    const float* W;
    const float* bias;
    float* out;
    if (p == 0)      { W = Wq; bias = bq; out = g_q; }
    else if (p == 1) { W = Wk; bias = bk; out = g_k; }
    else             { W = Wv; bias = bv; out = g_v; }
    W += (size_t)h * DIN * DH;
    bias += h * DH;

    __shared__ float As[BK][BM + 4];  // [32][132], k-major-transposed
    __shared__ float Bs[BK][BN];      // [32][64]

    const int tid = threadIdx.x;
    const int m0 = blockIdx.x * BM;

    const int tm = (tid / 16) * 8;   // 0..120
    const int tn = (tid % 16) * 4;   // 0..60

    const int ar = tid / 8;          // 0..31 (A loader row base)
    const int ac = (tid % 8) * 4;    // 0..28 (A loader col)
    const int br = tid / 16;         // 0..15
    const int bc = (tid % 16) * 4;   // 0..60

    float acc[8][4] = {};

    for (int k0 = 0; k0 < DIN; k0 += BK) {
        // A tile: 128 rows x 32 k, stored transposed As[kk][m]
        #pragma unroll
        for (int r = 0; r < 4; r++) {
            int row = ar + r * 32;
            float4 v = *(const float4*)(x + (size_t)(m0 + row) * DIN + k0 + ac);
            As[ac + 0][row] = v.x;
            As[ac + 1][row] = v.y;
            As[ac + 2][row] = v.z;
            As[ac + 3][row] = v.w;
        }
        // B tile: 32 k x 64 n (natural)
        #pragma unroll
        for (int r = 0; r < 2; r++) {
            int row = br + r * 16;
            *(float4*)&Bs[row][bc] = *(const float4*)(W + (size_t)(k0 + row) * DH + bc);
        }
        __syncthreads();

        #pragma unroll
        for (int kk = 0; kk < BK; kk++) {
            float a[8], b[4];
            *(float4*)&a[0] = *(const float4*)&As[kk][tm];
            *(float4*)&a[4] = *(const float4*)&As[kk][tm + 4];
            *(float4*)&b[0] = *(const float4*)&Bs[kk][tn];
            #pragma unroll
            for (int i = 0; i < 8; i++)
                #pragma unroll
                for (int j = 0; j < 4; j++)
                    acc[i][j] += a[i] * b[j];
        }
        __syncthreads();
    }

    // epilogue: bias + scatter to [B,H,S,64]
    float4 bv4 = *(const float4*)(bias + tn);
    #pragma unroll
    for (int i = 0; i < 8; i++) {
        int m = m0 + tm + i;
        int bb = m >> 11;        // /2048
        int s  = m & 2047;
        size_t base = (((size_t)bb * HEADS + h) * S_LEN + s) * DH + tn;
        float4 ov;
        ov.x = acc[i][0] + bv4.x;
        ov.y = acc[i][1] + bv4.y;
        ov.z = acc[i][2] + bv4.z;
        ov.w = acc[i][3] + bv4.w;
        *(float4*)(out + base) = ov;
    }
}

// ======================= Flash attention =======================
// grid: (S/64 q-tiles, B*H). block 256. Causal: kv tiles 0..qt.
// Online softmax; Q,K,Vt,P tiles in smem (stride 68 to dodge conflicts).
#define FSTR 68
#define FLASH_SMEM (4 * 64 * FSTR * 4)  // 69632 B

__global__ __launch_bounds__(256) void flash_kernel()
{
    extern __shared__ float sm[];
    float* Qs = sm;                 // [64][68]  Qs[q][d]
    float* Ks = Qs + 64 * FSTR;     // [64][68]  Ks[k][d]
    float* Vt = Ks + 64 * FSTR;     // [64][68]  Vt[d][k]  (transposed)
    float* Ps = Vt + 64 * FSTR;     // [64][68]  Ps[q][k]

    const int tid = threadIdx.x;
    const int qt = blockIdx.x;      // q tile
    const int bh = blockIdx.y;      // b*H + h
    const size_t base = (size_t)bh * S_LEN * DH;

    const int tx = tid & 15;        // 16 col-groups of 4
    const int ty = tid >> 4;        // 16 row-groups of 4

    // load Q tile
    {
        int r = tid >> 2;           // 0..63
        int c = (tid & 3) * 4;
        #pragma unroll
        for (int i = 0; i < 4; i++)
            *(float4*)&Qs[r * FSTR + c + i * 16] =
                *(const float4*)(g_q + base + (size_t)(qt * 64 + r) * DH + c + i * 16);
    }

    float m_i[4], l_i[4];
    float o[4][4] = {};
    #pragma unroll
    for (int i = 0; i < 4; i++) { m_i[i] = -1e30f; l_i[i] = 0.f; }

    for (int kt = 0; kt <= qt; kt++) {
        __syncthreads();  // prev Ps/Vt reads done (also covers Q store on first iter)

        // load K tile (natural) and V tile (transposed)
        {
            int r = tid >> 2;
            int c4 = tid & 3;
            #pragma unroll
            for (int i = 0; i < 4; i++) {
                int c = (c4 + i * 4) * 4;
                float4 k4 = *(const float4*)(g_k + base + (size_t)(kt * 64 + r) * DH + c);
                *(float4*)&Ks[r * FSTR + c] = k4;
                float4 v4 = *(const float4*)(g_v + base + (size_t)(kt * 64 + r) * DH + c);
                Vt[(c + 0) * FSTR + r] = v4.x;
                Vt[(c + 1) * FSTR + r] = v4.y;
                Vt[(c + 2) * FSTR + r] = v4.z;
                Vt[(c + 3) * FSTR + r] = v4.w;
            }
        }
        __syncthreads();

        // scores: s[i][j] = Q[ty*4+i] . K[tx*4+j]
        float s[4][4] = {};
        #pragma unroll
        for (int d = 0; d < DH; d += 4) {
            float4 q4[4], k4[4];
            #pragma unroll
            for (int i = 0; i < 4; i++)
                q4[i] = *(const float4*)&Qs[(ty * 4 + i) * FSTR + d];
            #pragma unroll
            for (int j = 0; j < 4; j++)
                k4[j] = *(const float4*)&Ks[(tx * 4 + j) * FSTR + d];
            #pragma unroll
            for (int i = 0; i < 4; i++)
                #pragma unroll
                for (int j = 0; j < 4; j++)
                    s[i][j] += q4[i].x * k4[j].x + q4[i].y * k4[j].y +
                               q4[i].z * k4[j].z + q4[i].w * k4[j].w;
        }

        const float scale = 0.125f;  // 1/sqrt(64)
        const bool diag = (kt == qt);
        #pragma unroll
        for (int i = 0; i < 4; i++)
            #pragma unroll
            for (int j = 0; j < 4; j++) {
                s[i][j] *= scale;
                if (diag && (tx * 4 + j) > (ty * 4 + i)) s[i][j] = -1e30f;
            }

        // online softmax (row reduce across the 16 tx lanes)
        #pragma unroll
        for (int i = 0; i < 4; i++) {
            float mx = fmaxf(fmaxf(s[i][0], s[i][1]), fmaxf(s[i][2], s[i][3]));
            #pragma unroll
            for (int off = 8; off >= 1; off >>= 1)
                mx = fmaxf(mx, __shfl_xor_sync(0xffffffffu, mx, off, 16));
            float m_new = fmaxf(m_i[i], mx);
            float alpha = __expf(m_i[i] - m_new);
            float sum = 0.f;
            #pragma unroll
            for (int j = 0; j < 4; j++) {
                float pv = __expf(s[i][j] - m_new);
                s[i][j] = pv;
                sum += pv;
            }
            #pragma unroll
            for (int off = 8; off >= 1; off >>= 1)
                sum += __shfl_xor_sync(0xffffffffu, sum, off, 16);
            l_i[i] = l_i[i] * alpha + sum;
            m_i[i] = m_new;
            #pragma unroll
            for (int j = 0; j < 4; j++) o[i][j] *= alpha;
        }

        // stage P tile
        #pragma unroll
        for (int i = 0; i < 4; i++) {
            float4 pv = make_float4(s[i][0], s[i][1], s[i][2], s[i][3]);
            *(float4*)&Ps[(ty * 4 + i) * FSTR + tx * 4] = pv;
        }
        __syncthreads();

        // O += P . V  (Vt is [d][k])
        #pragma unroll
        for (int kk = 0; kk < 64; kk += 4) {
            float4 p4[4], v4[4];
            #pragma unroll
            for (int i = 0; i < 4; i++)
                p4[i] = *(const float4*)&Ps[(ty * 4 + i) * FSTR + kk];
            #pragma unroll
            for (int j = 0; j < 4; j++)
                v4[j] = *(const float4*)&Vt[(tx * 4 + j) * FSTR + kk];
            #pragma unroll
            for (int i = 0; i < 4; i++)
                #pragma unroll
                for (int j = 0; j < 4; j++)
                    o[i][j] += p4[i].x * v4[j].x + p4[i].y * v4[j].y +
                               p4[i].z * v4[j].z + p4[i].w * v4[j].w;
        }
    }

    // epilogue: normalize + write concat-head layout [m][h*64+e]
    const int b = bh >> 4;
    const int h = bh & 15;
    #pragma unroll
    for (int i = 0; i < 4; i++) {
        float inv = 1.f / l_i[i];
        int row = qt * 64 + ty * 4 + i;
        size_t idx = ((size_t)(b * S_LEN + row)) * (HEADS * DH) + h * DH + tx * 4;
        float4 ov = make_float4(o[i][0] * inv, o[i][1] * inv, o[i][2] * inv, o[i][3] * inv);
        *(float4*)(g_attn + idx) = ov;
    }
}

// ======================= Output projection =======================
// [8192 x 1024] x [1024 x 64] + bo -> d_out. grid (64), block 256.
__global__ __launch_bounds__(256) void out_gemm(
    const float* __restrict__ Wo, const float* __restrict__ bo,
    float* __restrict__ out)
{
    __shared__ float As[BK][BM + 4];
    __shared__ float Bs[BK][BN];

    const int tid = threadIdx.x;
    const int m0 = blockIdx.x * BM;

    const int tm = (tid / 16) * 8;
    const int tn = (tid % 16) * 4;
    const int ar = tid / 8;
    const int ac = (tid % 8) * 4;
    const int br = tid / 16;
    const int bc = (tid % 16) * 4;

    float acc[8][4] = {};

    for (int k0 = 0; k0 < DIN; k0 += BK) {
        #pragma unroll
        for (int r = 0; r < 4; r++) {
            int row = ar + r * 32;
            float4 v = *(const float4*)(g_attn + (size_t)(m0 + row) * DIN + k0 + ac);
            As[ac + 0][row] = v.x;
            As[ac + 1][row] = v.y;
            As[ac + 2][row] = v.z;
            As[ac + 3][row] = v.w;
        }
        #pragma unroll
        for (int r = 0; r < 2; r++) {
            int row = br + r * 16;
            *(float4*)&Bs[row][bc] = *(const float4*)(Wo + (size_t)(k0 + row) * DH + bc);
        }
        __syncthreads();

        #pragma unroll
        for (int kk = 0; kk < BK; kk++) {
            float a[8], b[4];
            *(float4*)&a[0] = *(const float4*)&As[kk][tm];
            *(float4*)&a[4] = *(const float4*)&As[kk][tm + 4];
            *(float4*)&b[0] = *(const float4*)&Bs[kk][tn];
            #pragma unroll
            for (int i = 0; i < 8; i++)
                #pragma unroll
                for (int j = 0; j < 4; j++)
                    acc[i][j] += a[i] * b[j];
        }
        __syncthreads();
    }

    float4 bv4 = *(const float4*)(bo + tn);
    #pragma unroll
    for (int i = 0; i < 8; i++) {
        int m = m0 + tm + i;
        float4 ov;
        ov.x = acc[i][0] + bv4.x;
        ov.y = acc[i][1] + bv4.y;
        ov.z = acc[i][2] + bv4.z;
        ov.w = acc[i][3] + bv4.w;
        *(float4*)(out + (size_t)m * DH + tn) = ov;
    }
}

// ======================= launch =======================
extern "C" void kernel_launch(void* const* d_in, const int* in_sizes, int n_in,
                              void* d_out, int out_size)
{
    const float* x  = (const float*)d_in[0];
    const float* Wq = (const float*)d_in[1];
    const float* bq = (const float*)d_in[2];
    const float* Wk = (const float*)d_in[3];
    const float* bk = (const float*)d_in[4];
    const float* Wv = (const float*)d_in[5];
    const float* bv = (const float*)d_in[6];
    const float* Wo = (const float*)d_in[7];
    const float* bo = (const float*)d_in[8];
    float* out = (float*)d_out;

    cudaFuncSetAttribute(flash_kernel,
                         cudaFuncAttributeMaxDynamicSharedMemorySize, FLASH_SMEM);

    dim3 g1(M_TOT / BM, HEADS, 3);
    qkv_gemm<<<g1, 256>>>(x, Wq, bq, Wk, bk, Wv, bv);

    dim3 g2(S_LEN / 64, BATCH * HEADS);
    flash_kernel<<<g2, 256, FLASH_SMEM>>>();

    out_gemm<<<M_TOT / BM, 256>>>(Wo, bo, out);
}

// round 2
// speedup vs baseline: 4.9399x; 4.9399x over previous
#include <cuda_runtime.h>

#define S_LEN 2048
#define BATCH 4
#define HEADS 16
#define DH 64
#define DIN 1024
#define M_TOT (BATCH * S_LEN)  // 8192

// ---------------- scratch (allocation-free) ----------------
__device__ float g_q[BATCH * HEADS * S_LEN * DH];   // [B,H,S,64] fp32
__device__ float g_k[BATCH * HEADS * S_LEN * DH];
__device__ float g_v[BATCH * HEADS * S_LEN * DH];
__device__ float g_attn[M_TOT * HEADS * DH];        // [m][h*64+e] fp32

// ---------------- tf32 helpers ----------------
__device__ __forceinline__ unsigned f2tf(float f) {
    unsigned r;
    asm("cvt.rna.tf32.f32 %0, %1;" : "=r"(r) : "f"(f));
    return r;
}

__device__ __forceinline__ void mma_tf32(float* c, unsigned a0, unsigned a1,
                                         unsigned a2, unsigned a3,
                                         unsigned b0, unsigned b1) {
    asm volatile(
        "mma.sync.aligned.m16n8k8.row.col.f32.tf32.tf32.f32 "
        "{%0,%1,%2,%3}, {%4,%5,%6,%7}, {%8,%9}, {%0,%1,%2,%3};\n"
        : "+f"(c[0]), "+f"(c[1]), "+f"(c[2]), "+f"(c[3])
        : "r"(a0), "r"(a1), "r"(a2), "r"(a3), "r"(b0), "r"(b1));
}

// ======================= QKV projection (tf32 MMA) =======================
// grid (64 m-tiles, 8 head-pairs, 3 {q,k,v}); block 256 (8 warps, 4M x 2N).
// Block tile 128x128 (two heads), warp tile 32x64 (one head).
#define QBM 128
#define QBK 32
#define ASTR 36    // ≡ 4 (mod 32): A-frag bank = 4g+t, conflict-free
#define BSTR 136   // ≡ 8 (mod 32): B-frag bank = 8t+g, conflict-free

__global__ __launch_bounds__(256) void qkv_gemm(
    const float* __restrict__ x,
    const float* __restrict__ Wq, const float* __restrict__ bq,
    const float* __restrict__ Wk, const float* __restrict__ bk,
    const float* __restrict__ Wv, const float* __restrict__ bv)
{
    const int p = blockIdx.z;
    const int hp = blockIdx.y;           // head pair: heads 2hp, 2hp+1
    const float* W; const float* bias; float* out;
    if (p == 0)      { W = Wq; bias = bq; out = g_q; }
    else if (p == 1) { W = Wk; bias = bk; out = g_k; }
    else             { W = Wv; bias = bv; out = g_v; }
    const float* W0 = W + (size_t)(2 * hp) * DIN * DH;

    __shared__ unsigned As[QBM * ASTR];
    __shared__ unsigned Bs[QBK * BSTR];

    const int tid = threadIdx.x;
    const int w = tid >> 5, lane = tid & 31;
    const int g = lane >> 2, t = lane & 3;
    const int wm = w >> 1, wn = w & 1;   // warp m 0..3, n 0..1
    const int m0 = blockIdx.x * QBM;

    float acc[2][8][4] = {};

    for (int k0 = 0; k0 < DIN; k0 += QBK) {
        __syncthreads();
        // A tile 128x32, convert to tf32
        {
            int r = tid >> 3, kc = (tid & 7) * 4;
            #pragma unroll
            for (int it = 0; it < 4; it++) {
                int row = r + 32 * it;
                float4 v = *(const float4*)(x + (size_t)(m0 + row) * DIN + k0 + kc);
                *(uint4*)&As[row * ASTR + kc] =
                    make_uint4(f2tf(v.x), f2tf(v.y), f2tf(v.z), f2tf(v.w));
            }
        }
        // B tile 32x128 (two heads side by side)
        {
            int r = tid >> 5, n = (tid & 31) * 4;
            int hh = n >> 6, e = n & 63;
            const float* Wp = W0 + (size_t)hh * DIN * DH;
            #pragma unroll
            for (int it = 0; it < 4; it++) {
                int row = r + 8 * it;
                float4 v = *(const float4*)(Wp + (size_t)(k0 + row) * DH + e);
                *(uint4*)&Bs[row * BSTR + n] =
                    make_uint4(f2tf(v.x), f2tf(v.y), f2tf(v.z), f2tf(v.w));
            }
        }
        __syncthreads();

        #pragma unroll
        for (int ks = 0; ks < 4; ks++) {
            unsigned a[2][4];
            #pragma unroll
            for (int mi = 0; mi < 2; mi++) {
                int r0 = (32 * wm + 16 * mi + g) * ASTR + 8 * ks;
                int r1 = r0 + 8 * ASTR;
                a[mi][0] = As[r0 + t];
                a[mi][1] = As[r1 + t];
                a[mi][2] = As[r0 + t + 4];
                a[mi][3] = As[r1 + t + 4];
            }
            #pragma unroll
            for (int nf = 0; nf < 8; nf++) {
                int n = 64 * wn + 8 * nf + g;
                unsigned b0 = Bs[(8 * ks + t) * BSTR + n];
                unsigned b1 = Bs[(8 * ks + t + 4) * BSTR + n];
                mma_tf32(acc[0][nf], a[0][0], a[0][1], a[0][2], a[0][3], b0, b1);
                mma_tf32(acc[1][nf], a[1][0], a[1][1], a[1][2], a[1][3], b0, b1);
            }
        }
    }

    // epilogue: bias + scatter to [B,H,S,64]
    const int head = 2 * hp + wn;
    const float* bp = bias + head * DH;
    #pragma unroll
    for (int mi = 0; mi < 2; mi++) {
        #pragma unroll
        for (int nf = 0; nf < 8; nf++) {
            int e = 8 * nf + 2 * t;
            float be0 = bp[e], be1 = bp[e + 1];
            int row = m0 + 32 * wm + 16 * mi + g;
            #pragma unroll
            for (int rr = 0; rr < 2; rr++) {
                int m = row + 8 * rr;
                int bb = m >> 11, s = m & 2047;
                size_t base = (((size_t)bb * HEADS + head) * S_LEN + s) * DH + e;
                float2 ov = make_float2(acc[mi][nf][2 * rr] + be0,
                                        acc[mi][nf][2 * rr + 1] + be1);
                *(float2*)(out + base) = ov;
            }
        }
    }
}

// ======================= Flash attention (tf32 MMA) =======================
// grid (32 q-tiles, 64 bh); block 128 (4 warps, 16 q-rows each).
#define FQ 68   // Qs/Ps/Ks stride (≡4 mod 32)
#define FB 72   // Vs stride (≡8 mod 32)
#define ATT_SMEM ((64 * FQ * 3 + 64 * FB) * 4)

__global__ __launch_bounds__(128) void flash_kernel()
{
    extern __shared__ unsigned sm[];
    unsigned* Qs = sm;               // [64][FQ] q-major (A-frag: g in row)
    unsigned* Ks = Qs + 64 * FQ;     // [64][FQ] kv-major (B-frag: g in row)
    unsigned* Vs = Ks + 64 * FQ;     // [64][FB] kv-major (B-frag: t in row)
    unsigned* Ps = Vs + 64 * FB;     // [64][FQ] q-major

    const int tid = threadIdx.x;
    const int w = tid >> 5, lane = tid & 31;
    const int g = lane >> 2, t = lane & 3;
    const int qt = blockIdx.x;
    const int bh = blockIdx.y;
    const size_t base = (size_t)bh * S_LEN * DH;

    // load Q tile, fold 1/sqrt(64) scale, convert tf32
    #pragma unroll
    for (int i = 0; i < 8; i++) {
        int slot = tid + i * 128;
        int row = slot >> 4, c = (slot & 15) * 4;
        float4 v = *(const float4*)(g_q + base + (size_t)(qt * 64 + row) * DH + c);
        *(uint4*)&Qs[row * FQ + c] = make_uint4(
            f2tf(v.x * 0.125f), f2tf(v.y * 0.125f),
            f2tf(v.z * 0.125f), f2tf(v.w * 0.125f));
    }

    float m_i[2] = {-1e30f, -1e30f};
    float l_i[2] = {0.f, 0.f};
    float o[8][4] = {};

    for (int kt = 0; kt <= qt; kt++) {
        __syncthreads();   // protect Ks/Vs (and Qs first iter)
        // load K (natural) and V (natural) tiles as tf32
        #pragma unroll
        for (int i = 0; i < 8; i++) {
            int slot = tid + i * 128;
            int row = slot >> 4, c = (slot & 15) * 4;
            float4 kv = *(const float4*)(g_k + base + (size_t)(kt * 64 + row) * DH + c);
            *(uint4*)&Ks[row * FQ + c] =
                make_uint4(f2tf(kv.x), f2tf(kv.y), f2tf(kv.z), f2tf(kv.w));
            float4 vv = *(const float4*)(g_v + base + (size_t)(kt * 64 + row) * DH + c);
            *(uint4*)&Vs[row * FB + c] =
                make_uint4(f2tf(vv.x), f2tf(vv.y), f2tf(vv.z), f2tf(vv.w));
        }
        __syncthreads();

        // S = Q K^T : warp rows 16w..16w+15, cols 0..63
        float c_[8][4] = {};
        #pragma unroll
        for (int ks = 0; ks < 8; ks++) {
            int r0 = (16 * w + g) * FQ + 8 * ks;
            int r1 = r0 + 8 * FQ;
            unsigned a0 = Qs[r0 + t], a1 = Qs[r1 + t];
            unsigned a2 = Qs[r0 + t + 4], a3 = Qs[r1 + t + 4];
            #pragma unroll
            for (int nf = 0; nf < 8; nf++) {
                unsigned b0 = Ks[(8 * nf + g) * FQ + 8 * ks + t];
                unsigned b1 = Ks[(8 * nf + g) * FQ + 8 * ks + t + 4];
                mma_tf32(c_[nf], a0, a1, a2, a3, b0, b1);
            }
        }

        // causal mask on diagonal tile
        if (kt == qt) {
            int rl0 = 16 * w + g, rl1 = rl0 + 8;
            #pragma unroll
            for (int nf = 0; nf < 8; nf++) {
                int col = 8 * nf + 2 * t;
                if (col > rl0)     c_[nf][0] = -1e30f;
                if (col + 1 > rl0) c_[nf][1] = -1e30f;
                if (col > rl1)     c_[nf][2] = -1e30f;
                if (col + 1 > rl1) c_[nf][3] = -1e30f;
            }
        }

        // online softmax, rows r0 (regs 0,1) and r1 (regs 2,3)
        float alpha[2];
        #pragma unroll
        for (int rr = 0; rr < 2; rr++) {
            float mx = -1e30f;
            #pragma unroll
            for (int nf = 0; nf < 8; nf++)
                mx = fmaxf(mx, fmaxf(c_[nf][2 * rr], c_[nf][2 * rr + 1]));
            mx = fmaxf(mx, __shfl_xor_sync(0xffffffffu, mx, 1));
            mx = fmaxf(mx, __shfl_xor_sync(0xffffffffu, mx, 2));
            float m_new = fmaxf(m_i[rr], mx);
            alpha[rr] = __expf(m_i[rr] - m_new);
            float sum = 0.f;
            #pragma unroll
            for (int nf = 0; nf < 8; nf++) {
                float p0 = __expf(c_[nf][2 * rr] - m_new);
                float p1 = __expf(c_[nf][2 * rr + 1] - m_new);
                c_[nf][2 * rr] = p0; c_[nf][2 * rr + 1] = p1;
                sum += p0 + p1;
            }
            sum += __shfl_xor_sync(0xffffffffu, sum, 1);
            sum += __shfl_xor_sync(0xffffffffu, sum, 2);
            l_i[rr] = l_i[rr] * alpha[rr] + sum;
            m_i[rr] = m_new;
        }

        // stage P (tf32) — rows are warp-private
        #pragma unroll
        for (int nf = 0; nf < 8; nf++) {
            int col = 8 * nf + 2 * t;
            *(uint2*)&Ps[(16 * w + g) * FQ + col] =
                make_uint2(f2tf(c_[nf][0]), f2tf(c_[nf][1]));
            *(uint2*)&Ps[(16 * w + g + 8) * FQ + col] =
                make_uint2(f2tf(c_[nf][2]), f2tf(c_[nf][3]));
        }
        __syncwarp();

        // rescale O, then O += P V
        #pragma unroll
        for (int nf = 0; nf < 8; nf++) {
            o[nf][0] *= alpha[0]; o[nf][1] *= alpha[0];
            o[nf][2] *= alpha[1]; o[nf][3] *= alpha[1];
        }
        #pragma unroll
        for (int ks = 0; ks < 8; ks++) {
            int r0 = (16 * w + g) * FQ + 8 * ks;
            int r1 = r0 + 8 * FQ;
            unsigned a0 = Ps[r0 + t], a1 = Ps[r1 + t];
            unsigned a2 = Ps[r0 + t + 4], a3 = Ps[r1 + t + 4];
            #pragma unroll
            for (int nf = 0; nf < 8; nf++) {
                unsigned b0 = Vs[(8 * ks + t) * FB + 8 * nf + g];
                unsigned b1 = Vs[(8 * ks + t + 4) * FB + 8 * nf + g];
                mma_tf32(o[nf], a0, a1, a2, a3, b0, b1);
            }
        }
    }

    // epilogue: normalize + concat-head write [m][h*64+e]
    const int b = bh >> 4, h = bh & 15;
    float inv0 = 1.f / l_i[0], inv1 = 1.f / l_i[1];
    #pragma unroll
    for (int nf = 0; nf < 8; nf++) {
        int e = 8 * nf + 2 * t;
        int row = qt * 64 + 16 * w + g;
        size_t i0 = ((size_t)(b * S_LEN + row)) * (HEADS * DH) + h * DH + e;
        size_t i1 = ((size_t)(b * S_LEN + row + 8)) * (HEADS * DH) + h * DH + e;
        *(float2*)(g_attn + i0) = make_float2(o[nf][0] * inv0, o[nf][1] * inv0);
        *(float2*)(g_attn + i1) = make_float2(o[nf][2] * inv1, o[nf][3] * inv1);
    }
}

// ======================= Output projection (tf32 MMA) =======================
// [8192x1024] x [1024x64] + bo. grid 64, block 256 (8 warps 4M x 2N, warp 32x32).
#define OBSTR 72   // ≡ 8 (mod 32)

__global__ __launch_bounds__(256) void out_gemm(
    const float* __restrict__ Wo, const float* __restrict__ bo,
    float* __restrict__ outp)
{
    __shared__ unsigned As[QBM * ASTR];
    __shared__ unsigned Bs[QBK * OBSTR];

    const int tid = threadIdx.x;
    const int w = tid >> 5, lane = tid & 31;
    const int g = lane >> 2, t = lane & 3;
    const int wm = w >> 1, wn = w & 1;
    const int m0 = blockIdx.x * QBM;

    float acc[2][4][4] = {};

    for (int k0 = 0; k0 < DIN; k0 += QBK) {
        __syncthreads();
        {
            int r = tid >> 3, kc = (tid & 7) * 4;
            #pragma unroll
            for (int it = 0; it < 4; it++) {
                int row = r + 32 * it;
                float4 v = *(const float4*)(g_attn + (size_t)(m0 + row) * DIN + k0 + kc);
                *(uint4*)&As[row * ASTR + kc] =
                    make_uint4(f2tf(v.x), f2tf(v.y), f2tf(v.z), f2tf(v.w));
            }
        }
        {
            int r = tid >> 4, n = (tid & 15) * 4;   // 16 rows per pass x 2
            #pragma unroll
            for (int it = 0; it < 2; it++) {
                int row = r + 16 * it;
                float4 v = *(const float4*)(Wo + (size_t)(k0 + row) * DH + n);
                *(uint4*)&Bs[row * OBSTR + n] =
                    make_uint4(f2tf(v.x), f2tf(v.y), f2tf(v.z), f2tf(v.w));
            }
        }
        __syncthreads();

        #pragma unroll
        for (int ks = 0; ks < 4; ks++) {
            unsigned a[2][4];
            #pragma unroll
            for (int mi = 0; mi < 2; mi++) {
                int r0 = (32 * wm + 16 * mi + g) * ASTR + 8 * ks;
                int r1 = r0 + 8 * ASTR;
                a[mi][0] = As[r0 + t];
                a[mi][1] = As[r1 + t];
                a[mi][2] = As[r0 + t + 4];
                a[mi][3] = As[r1 + t + 4];
            }
            #pragma unroll
            for (int nf = 0; nf < 4; nf++) {
                int n = 32 * wn + 8 * nf + g;
                unsigned b0 = Bs[(8 * ks + t) * OBSTR + n];
                unsigned b1 = Bs[(8 * ks + t + 4) * OBSTR + n];
                mma_tf32(acc[0][nf], a[0][0], a[0][1], a[0][2], a[0][3], b0, b1);
                mma_tf32(acc[1][nf], a[1][0], a[1][1], a[1][2], a[1][3], b0, b1);
            }
        }
    }

    #pragma unroll
    for (int mi = 0; mi < 2; mi++) {
        #pragma unroll
        for (int nf = 0; nf < 4; nf++) {
            int e = 32 * wn + 8 * nf + 2 * t;
            float be0 = bo[e], be1 = bo[e + 1];
            int row = m0 + 32 * wm + 16 * mi + g;
            #pragma unroll
            for (int rr = 0; rr < 2; rr++) {
                int m = row + 8 * rr;
                *(float2*)(outp + (size_t)m * DH + e) =
                    make_float2(acc[mi][nf][2 * rr] + be0,
                                acc[mi][nf][2 * rr + 1] + be1);
            }
        }
    }
}

// ======================= launch =======================
extern "C" void kernel_launch(void* const* d_in, const int* in_sizes, int n_in,
                              void* d_out, int out_size)
{
    const float* x  = (const float*)d_in[0];
    const float* Wq = (const float*)d_in[1];
    const float* bq = (const float*)d_in[2];
    const float* Wk = (const float*)d_in[3];
    const float* bk = (const float*)d_in[4];
    const float* Wv = (const float*)d_in[5];
    const float* bv = (const float*)d_in[6];
    const float* Wo = (const float*)d_in[7];
    const float* bo = (const float*)d_in[8];
    float* outp = (float*)d_out;

    cudaFuncSetAttribute(flash_kernel,
                         cudaFuncAttributeMaxDynamicSharedMemorySize, ATT_SMEM);

    dim3 g1(M_TOT / QBM, HEADS / 2, 3);
    qkv_gemm<<<g1, 256>>>(x, Wq, bq, Wk, bk, Wv, bv);

    dim3 g2(S_LEN / 64, BATCH * HEADS);
    flash_kernel<<<g2, 128, ATT_SMEM>>>();

    out_gemm<<<M_TOT / QBM, 256>>>(Wo, bo, outp);
}

// round 3
// speedup vs baseline: 4.9594x; 1.0039x over previous
#include <cuda_runtime.h>

#define S_LEN 2048
#define BATCH 4
#define HEADS 16
#define DH 64
#define DIN 1024
#define M_TOT (BATCH * S_LEN)  // 8192

// ---------------- scratch (allocation-free) ----------------
__device__ float g_q[BATCH * HEADS * S_LEN * DH];   // [B,H,S,64] fp32
__device__ float g_k[BATCH * HEADS * S_LEN * DH];
__device__ float g_v[BATCH * HEADS * S_LEN * DH];
__device__ float g_attn[M_TOT * HEADS * DH];        // [m][h*64+e] fp32

// ---------------- tf32 helpers ----------------
__device__ __forceinline__ unsigned f2tf(float f) {
    unsigned r;
    asm("cvt.rna.tf32.f32 %0, %1;" : "=r"(r) : "f"(f));
    return r;
}
__device__ __forceinline__ uint4 cvt4(float4 v) {
    return make_uint4(f2tf(v.x), f2tf(v.y), f2tf(v.z), f2tf(v.w));
}
__device__ __forceinline__ void mma_tf32(float* c, unsigned a0, unsigned a1,
                                         unsigned a2, unsigned a3,
                                         unsigned b0, unsigned b1) {
    asm volatile(
        "mma.sync.aligned.m16n8k8.row.col.f32.tf32.tf32.f32 "
        "{%0,%1,%2,%3}, {%4,%5,%6,%7}, {%8,%9}, {%0,%1,%2,%3};\n"
        : "+f"(c[0]), "+f"(c[1]), "+f"(c[2]), "+f"(c[3])
        : "r"(a0), "r"(a1), "r"(a2), "r"(a3), "r"(b0), "r"(b1));
}

// ======================= QKV projection (pipelined tf32 MMA) =======================
// grid (32 m-tiles, 8 head-pairs, 3); block 256 (8 warps = 4M x 2N), warp 64x64.
// Double-buffered smem; global loads register-staged and overlapped with MMA.
#define QBM 256
#define QBK 32
#define QASTR 36     // == 4 mod 32: A frag bank 4g+t conflict-free
#define QBSTR 136    // == 8 mod 32: B frag bank 8t+g conflict-free
#define QA_WORDS (QBM * QASTR)   // 9216
#define QB_WORDS (QBK * QBSTR)   // 4352
#define QKV_SMEM ((QA_WORDS + QB_WORDS) * 2 * 4)  // 108544 B

__global__ __launch_bounds__(256, 1) void qkv_gemm(
    const float* __restrict__ x,
    const float* __restrict__ Wq, const float* __restrict__ bq,
    const float* __restrict__ Wk, const float* __restrict__ bk,
    const float* __restrict__ Wv, const float* __restrict__ bv)
{
    extern __shared__ unsigned qsm[];
    unsigned* As = qsm;                    // [2][256][36]
    unsigned* Bs = qsm + 2 * QA_WORDS;     // [2][32][136]

    const int p = blockIdx.z, hp = blockIdx.y;
    const float* W; const float* bias; float* out;
    if (p == 0)      { W = Wq; bias = bq; out = g_q; }
    else if (p == 1) { W = Wk; bias = bk; out = g_k; }
    else             { W = Wv; bias = bv; out = g_v; }
    const float* W0 = W + (size_t)(2 * hp) * DIN * DH;

    const int tid = threadIdx.x, w = tid >> 5, lane = tid & 31;
    const int g = lane >> 2, t = lane & 3;
    const int wm = w >> 1, wn = w & 1;
    const int m0 = blockIdx.x * QBM;

    const int la_r = tid >> 3, la_c = (tid & 7) * 4;   // A loader
    const int lb_r = tid >> 4, lb_n = (tid & 15) * 8;  // B loader
    const float* xA = x + (size_t)(m0 + la_r) * DIN + la_c;
    const float* WB = W0 + (size_t)(lb_n >> 6) * DIN * DH + (lb_n & 63);

    float4 areg[8], breg[4];

    // prologue: load + store tile 0
    #pragma unroll
    for (int it = 0; it < 8; it++)
        areg[it] = *(const float4*)(xA + (size_t)(32 * it) * DIN);
    #pragma unroll
    for (int it = 0; it < 2; it++) {
        const float* wp = WB + (size_t)(lb_r + 16 * it) * DH;
        breg[2 * it]     = *(const float4*)wp;
        breg[2 * it + 1] = *(const float4*)(wp + 4);
    }
    #pragma unroll
    for (int it = 0; it < 8; it++)
        *(uint4*)&As[(la_r + 32 * it) * QASTR + la_c] = cvt4(areg[it]);
    #pragma unroll
    for (int it = 0; it < 2; it++) {
        int row = lb_r + 16 * it;
        *(uint4*)&Bs[row * QBSTR + lb_n]     = cvt4(breg[2 * it]);
        *(uint4*)&Bs[row * QBSTR + lb_n + 4] = cvt4(breg[2 * it + 1]);
    }

    float acc[4][8][4] = {};
    const int NT = DIN / QBK;  // 32

    for (int tt = 0; tt < NT; tt++) {
        __syncthreads();
        if (tt + 1 < NT) {
            int k0 = (tt + 1) * QBK;
            #pragma unroll
            for (int it = 0; it < 8; it++)
                areg[it] = *(const float4*)(xA + k0 + (size_t)(32 * it) * DIN);
            #pragma unroll
            for (int it = 0; it < 2; it++) {
                const float* wp = WB + (size_t)(k0 + lb_r + 16 * it) * DH;
                breg[2 * it]     = *(const float4*)wp;
                breg[2 * it + 1] = *(const float4*)(wp + 4);
            }
        }
        const unsigned* Ab = As + (tt & 1) * QA_WORDS;
        const unsigned* Bb = Bs + (tt & 1) * QB_WORDS;
        #pragma unroll
        for (int ks = 0; ks < 4; ks++) {
            unsigned a[4][4];
            #pragma unroll
            for (int mi = 0; mi < 4; mi++) {
                int r0 = (64 * wm + 16 * mi + g) * QASTR + 8 * ks;
                int r1 = r0 + 8 * QASTR;
                a[mi][0] = Ab[r0 + t];     a[mi][1] = Ab[r1 + t];
                a[mi][2] = Ab[r0 + t + 4]; a[mi][3] = Ab[r1 + t + 4];
            }
            #pragma unroll
            for (int nf = 0; nf < 8; nf++) {
                int n = 64 * wn + 8 * nf + g;
                unsigned b0 = Bb[(8 * ks + t) * QBSTR + n];
                unsigned b1 = Bb[(8 * ks + t + 4) * QBSTR + n];
                #pragma unroll
                for (int mi = 0; mi < 4; mi++)
                    mma_tf32(acc[mi][nf], a[mi][0], a[mi][1], a[mi][2], a[mi][3], b0, b1);
            }
        }
        if (tt + 1 < NT) {
            __syncthreads();
            unsigned* Aw = As + ((tt + 1) & 1) * QA_WORDS;
            unsigned* Bw = Bs + ((tt + 1) & 1) * QB_WORDS;
            #pragma unroll
            for (int it = 0; it < 8; it++)
                *(uint4*)&Aw[(la_r + 32 * it) * QASTR + la_c] = cvt4(areg[it]);
            #pragma unroll
            for (int it = 0; it < 2; it++) {
                int row = lb_r + 16 * it;
                *(uint4*)&Bw[row * QBSTR + lb_n]     = cvt4(breg[2 * it]);
                *(uint4*)&Bw[row * QBSTR + lb_n + 4] = cvt4(breg[2 * it + 1]);
            }
        }
    }

    // epilogue: bias + scatter to [B,H,S,64]
    const int head = 2 * hp + wn;
    const float* bp = bias + head * DH;
    #pragma unroll
    for (int mi = 0; mi < 4; mi++) {
        #pragma unroll
        for (int nf = 0; nf < 8; nf++) {
            int e = 8 * nf + 2 * t;
            float be0 = bp[e], be1 = bp[e + 1];
            int row = m0 + 64 * wm + 16 * mi + g;
            #pragma unroll
            for (int rr = 0; rr < 2; rr++) {
                int m = row + 8 * rr;
                int bb = m >> 11, s = m & 2047;
                size_t base = (((size_t)bb * HEADS + head) * S_LEN + s) * DH + e;
                *(float2*)(out + base) =
                    make_float2(acc[mi][nf][4 * 0 + 2 * rr] + be0,
                                acc[mi][nf][2 * rr + 1] + be1);
            }
        }
    }
}

// ======================= Flash attention (tf32 MMA, 128-row q-tiles) =======================
// grid (16 q-tiles, 64 bh); block 128 (4 warps x 32 q-rows). KV tile 64.
// Q fragments register-resident; P buffer aliases Q staging (warp-private rows).
#define FK 68    // == 4 mod 32
#define FV 72    // == 8 mod 32
#define FP 68
#define K_WORDS (64 * FK)    // 4352
#define V_WORDS (64 * FV)    // 4608
#define P_WORDS (128 * FP)   // 8704
#define ATT_SMEM ((K_WORDS + V_WORDS + P_WORDS) * 4)  // 70656 B

__global__ __launch_bounds__(128, 1) void flash_kernel()
{
    extern __shared__ unsigned sm[];
    unsigned* Ks = sm;
    unsigned* Vs = Ks + K_WORDS;
    unsigned* Ps = Vs + V_WORDS;   // also Q staging

    const int tid = threadIdx.x, w = tid >> 5, lane = tid & 31;
    const int g = lane >> 2, t = lane & 3;
    const int qt = (int)(gridDim.x - 1 - blockIdx.x);   // big tiles first
    const int bh = blockIdx.y;
    const size_t base = (size_t)bh * S_LEN * DH;
    const int qrow0 = qt * 128;

    // stage Q (128x64) into Ps with scale folded, then hoist fragments to regs
    #pragma unroll
    for (int i = 0; i < 16; i++) {
        int slot = tid + i * 128;
        int row = slot >> 4, c = (slot & 15) * 4;
        float4 v = *(const float4*)(g_q + base + (size_t)(qrow0 + row) * DH + c);
        *(uint4*)&Ps[row * FP + c] = make_uint4(
            f2tf(v.x * 0.125f), f2tf(v.y * 0.125f),
            f2tf(v.z * 0.125f), f2tf(v.w * 0.125f));
    }
    __syncthreads();
    unsigned qf[2][8][4];
    #pragma unroll
    for (int mi = 0; mi < 2; mi++)
        #pragma unroll
        for (int ks = 0; ks < 8; ks++) {
            int r0 = (32 * w + 16 * mi + g) * FP + 8 * ks;
            int r1 = r0 + 8 * FP;
            qf[mi][ks][0] = Ps[r0 + t];     qf[mi][ks][1] = Ps[r1 + t];
            qf[mi][ks][2] = Ps[r0 + t + 4]; qf[mi][ks][3] = Ps[r1 + t + 4];
        }

    float m_i[4] = {-1e30f, -1e30f, -1e30f, -1e30f};
    float l_i[4] = {0.f, 0.f, 0.f, 0.f};
    float o[2][8][4] = {};

    const int ktmax = 2 * qt + 1;
    for (int kt = 0; kt <= ktmax; kt++) {
        __syncthreads();   // prior K/V reads done
        #pragma unroll
        for (int i = 0; i < 8; i++) {
            int slot = tid + i * 128;
            int row = slot >> 4, c = (slot & 15) * 4;
            float4 kv = *(const float4*)(g_k + base + (size_t)(kt * 64 + row) * DH + c);
            *(uint4*)&Ks[row * FK + c] =
                make_uint4(f2tf(kv.x), f2tf(kv.y), f2tf(kv.z), f2tf(kv.w));
            float4 vv = *(const float4*)(g_v + base + (size_t)(kt * 64 + row) * DH + c);
            *(uint4*)&Vs[row * FV + c] =
                make_uint4(f2tf(vv.x), f2tf(vv.y), f2tf(vv.z), f2tf(vv.w));
        }
        __syncthreads();

        // S = Q K^T : warp rows 32w..32w+31, cols 0..63
        float c_[2][8][4] = {};
        #pragma unroll
        for (int ks = 0; ks < 8; ks++) {
            #pragma unroll
            for (int nf = 0; nf < 8; nf++) {
                unsigned b0 = Ks[(8 * nf + g) * FK + 8 * ks + t];
                unsigned b1 = Ks[(8 * nf + g) * FK + 8 * ks + t + 4];
                mma_tf32(c_[0][nf], qf[0][ks][0], qf[0][ks][1], qf[0][ks][2], qf[0][ks][3], b0, b1);
                mma_tf32(c_[1][nf], qf[1][ks][0], qf[1][ks][1], qf[1][ks][2], qf[1][ks][3], b0, b1);
            }
        }

        // causal mask (only last two kv tiles touch the diagonal)
        if (kt >= 2 * qt) {
            int colbase = kt * 64;
            #pragma unroll
            for (int mi = 0; mi < 2; mi++) {
                int r0 = qrow0 + 32 * w + 16 * mi + g;
                #pragma unroll
                for (int nf = 0; nf < 8; nf++) {
                    int col = colbase + 8 * nf + 2 * t;
                    if (col     > r0)     c_[mi][nf][0] = -1e30f;
                    if (col + 1 > r0)     c_[mi][nf][1] = -1e30f;
                    if (col     > r0 + 8) c_[mi][nf][2] = -1e30f;
                    if (col + 1 > r0 + 8) c_[mi][nf][3] = -1e30f;
                }
            }
        }

        // online softmax: 4 rows/thread (mi x {g, g+8})
        float alpha[4];
        #pragma unroll
        for (int mi = 0; mi < 2; mi++)
            #pragma unroll
            for (int hh = 0; hh < 2; hh++) {
                int rr = 2 * mi + hh;
                float mx = -1e30f;
                #pragma unroll
                for (int nf = 0; nf < 8; nf++)
                    mx = fmaxf(mx, fmaxf(c_[mi][nf][2 * hh], c_[mi][nf][2 * hh + 1]));
                mx = fmaxf(mx, __shfl_xor_sync(0xffffffffu, mx, 1));
                mx = fmaxf(mx, __shfl_xor_sync(0xffffffffu, mx, 2));
                float m_new = fmaxf(m_i[rr], mx);
                alpha[rr] = __expf(m_i[rr] - m_new);
                float sum = 0.f;
                #pragma unroll
                for (int nf = 0; nf < 8; nf++) {
                    float p0 = __expf(c_[mi][nf][2 * hh] - m_new);
                    float p1 = __expf(c_[mi][nf][2 * hh + 1] - m_new);
                    c_[mi][nf][2 * hh] = p0; c_[mi][nf][2 * hh + 1] = p1;
                    sum += p0 + p1;
                }
                sum += __shfl_xor_sync(0xffffffffu, sum, 1);
                sum += __shfl_xor_sync(0xffffffffu, sum, 2);
                l_i[rr] = l_i[rr] * alpha[rr] + sum;
                m_i[rr] = m_new;
            }

        // stage P (warp-private rows) + rescale O
        #pragma unroll
        for (int mi = 0; mi < 2; mi++) {
            int pr = (32 * w + 16 * mi + g) * FP;
            #pragma unroll
            for (int nf = 0; nf < 8; nf++) {
                int col = 8 * nf + 2 * t;
                *(uint2*)&Ps[pr + col] =
                    make_uint2(f2tf(c_[mi][nf][0]), f2tf(c_[mi][nf][1]));
                *(uint2*)&Ps[pr + 8 * FP + col] =
                    make_uint2(f2tf(c_[mi][nf][2]), f2tf(c_[mi][nf][3]));
            }
        }
        #pragma unroll
        for (int mi = 0; mi < 2; mi++)
            #pragma unroll
            for (int nf = 0; nf < 8; nf++) {
                o[mi][nf][0] *= alpha[2 * mi];     o[mi][nf][1] *= alpha[2 * mi];
                o[mi][nf][2] *= alpha[2 * mi + 1]; o[mi][nf][3] *= alpha[2 * mi + 1];
            }
        __syncwarp();

        // O += P V
        #pragma unroll
        for (int ks = 0; ks < 8; ks++) {
            unsigned a[2][4];
            #pragma unroll
            for (int mi = 0; mi < 2; mi++) {
                int r0 = (32 * w + 16 * mi + g) * FP + 8 * ks;
                int r1 = r0 + 8 * FP;
                a[mi][0] = Ps[r0 + t];     a[mi][1] = Ps[r1 + t];
                a[mi][2] = Ps[r0 + t + 4]; a[mi][3] = Ps[r1 + t + 4];
            }
            #pragma unroll
            for (int nf = 0; nf < 8; nf++) {
                unsigned b0 = Vs[(8 * ks + t) * FV + 8 * nf + g];
                unsigned b1 = Vs[(8 * ks + t + 4) * FV + 8 * nf + g];
                mma_tf32(o[0][nf], a[0][0], a[0][1], a[0][2], a[0][3], b0, b1);
                mma_tf32(o[1][nf], a[1][0], a[1][1], a[1][2], a[1][3], b0, b1);
            }
        }
        __syncwarp();   // P reads done before next iter's P writes
    }

    // epilogue: normalize + concat-head write [m][h*64+e]
    const int b = bh >> 4, h = bh & 15;
    #pragma unroll
    for (int mi = 0; mi < 2; mi++) {
        float inv0 = 1.f / l_i[2 * mi], inv1 = 1.f / l_i[2 * mi + 1];
        int row = qrow0 + 32 * w + 16 * mi + g;
        #pragma unroll
        for (int nf = 0; nf < 8; nf++) {
            int e = 8 * nf + 2 * t;
            size_t i0 = ((size_t)(b * S_LEN + row)) * (HEADS * DH) + h * DH + e;
            size_t i1 = ((size_t)(b * S_LEN + row + 8)) * (HEADS * DH) + h * DH + e;
            *(float2*)(g_attn + i0) = make_float2(o[mi][nf][0] * inv0, o[mi][nf][1] * inv0);
            *(float2*)(g_attn + i1) = make_float2(o[mi][nf][2] * inv1, o[mi][nf][3] * inv1);
        }
    }
}

// ======================= Output projection (tf32 MMA) =======================
#define OBM 128
#define OBK 32
#define OASTR 36
#define OBSTR 72

__global__ __launch_bounds__(256) void out_gemm(
    const float* __restrict__ Wo, const float* __restrict__ bo,
    float* __restrict__ outp)
{
    __shared__ unsigned As[OBM * OASTR];
    __shared__ unsigned Bs[OBK * OBSTR];

    const int tid = threadIdx.x, w = tid >> 5, lane = tid & 31;
    const int g = lane >> 2, t = lane & 3;
    const int wm = w >> 1, wn = w & 1;
    const int m0 = blockIdx.x * OBM;

    float acc[2][4][4] = {};

    for (int k0 = 0; k0 < DIN; k0 += OBK) {
        __syncthreads();
        {
            int r = tid >> 3, kc = (tid & 7) * 4;
            #pragma unroll
            for (int it = 0; it < 4; it++) {
                int row = r + 32 * it;
                float4 v = *(const float4*)(g_attn + (size_t)(m0 + row) * DIN + k0 + kc);
                *(uint4*)&As[row * OASTR + kc] = cvt4(v);
            }
        }
        {
            int r = tid >> 4, n = (tid & 15) * 4;
            #pragma unroll
            for (int it = 0; it < 2; it++) {
                int row = r + 16 * it;
                float4 v = *(const float4*)(Wo + (size_t)(k0 + row) * DH + n);
                *(uint4*)&Bs[row * OBSTR + n] = cvt4(v);
            }
        }
        __syncthreads();

        #pragma unroll
        for (int ks = 0; ks < 4; ks++) {
            unsigned a[2][4];
            #pragma unroll
            for (int mi = 0; mi < 2; mi++) {
                int r0 = (32 * wm + 16 * mi + g) * OASTR + 8 * ks;
                int r1 = r0 + 8 * OASTR;
                a[mi][0] = As[r0 + t];     a[mi][1] = As[r1 + t];
                a[mi][2] = As[r0 + t + 4]; a[mi][3] = As[r1 + t + 4];
            }
            #pragma unroll
            for (int nf = 0; nf < 4; nf++) {
                int n = 32 * wn + 8 * nf + g;
                unsigned b0 = Bs[(8 * ks + t) * OBSTR + n];
                unsigned b1 = Bs[(8 * ks + t + 4) * OBSTR + n];
                mma_tf32(acc[0][nf], a[0][0], a[0][1], a[0][2], a[0][3], b0, b1);
                mma_tf32(acc[1][nf], a[1][0], a[1][1], a[1][2], a[1][3], b0, b1);
            }
        }
    }

    #pragma unroll
    for (int mi = 0; mi < 2; mi++)
        #pragma unroll
        for (int nf = 0; nf < 4; nf++) {
            int e = 32 * wn + 8 * nf + 2 * t;
            float be0 = bo[e], be1 = bo[e + 1];
            int row = m0 + 32 * wm + 16 * mi + g;
            #pragma unroll
            for (int rr = 0; rr < 2; rr++) {
                int m = row + 8 * rr;
                *(float2*)(outp + (size_t)m * DH + e) =
                    make_float2(acc[mi][nf][2 * rr] + be0,
                                acc[mi][nf][2 * rr + 1] + be1);
            }
        }
}

// ======================= launch =======================
extern "C" void kernel_launch(void* const* d_in, const int* in_sizes, int n_in,
                              void* d_out, int out_size)
{
    const float* x  = (const float*)d_in[0];
    const float* Wq = (const float*)d_in[1];
    const float* bq = (const float*)d_in[2];
    const float* Wk = (const float*)d_in[3];
    const float* bk = (const float*)d_in[4];
    const float* Wv = (const float*)d_in[5];
    const float* bv = (const float*)d_in[6];
    const float* Wo = (const float*)d_in[7];
    const float* bo = (const float*)d_in[8];
    float* outp = (float*)d_out;

    cudaFuncSetAttribute(qkv_gemm,
                         cudaFuncAttributeMaxDynamicSharedMemorySize, QKV_SMEM);
    cudaFuncSetAttribute(flash_kernel,
                         cudaFuncAttributeMaxDynamicSharedMemorySize, ATT_SMEM);

    dim3 g1(M_TOT / QBM, HEADS / 2, 3);
    qkv_gemm<<<g1, 256, QKV_SMEM>>>(x, Wq, bq, Wk, bk, Wv, bv);

    dim3 g2(S_LEN / 128, BATCH * HEADS);
    flash_kernel<<<g2, 128, ATT_SMEM>>>();

    out_gemm<<<M_TOT / OBM, 256>>>(Wo, bo, outp);
}